// round 3
// baseline (speedup 1.0000x reference)
#include <cuda_runtime.h>

#define DIM 64
#define NROWS_BLK 128
#define NC_CHUNK 128
#define THREADS 256

// Deterministic per-block loss partial sums (N/128 = 2048 blocks max 4096)
__device__ float g_partials[4096];

// ---------- packed f32x2 helpers ----------
__device__ __forceinline__ unsigned long long pack2(float x, float y) {
    unsigned long long r;
    asm("mov.b64 %0, {%1, %2};" : "=l"(r) : "f"(x), "f"(y));
    return r;
}
__device__ __forceinline__ void unpack2(unsigned long long v, float& x, float& y) {
    asm("mov.b64 {%0, %1}, %2;" : "=f"(x), "=f"(y) : "l"(v));
}
__device__ __forceinline__ void fma2(unsigned long long& d, unsigned long long a, unsigned long long b) {
    asm("fma.rn.f32x2 %0, %1, %2, %0;" : "+l"(d) : "l"(a), "l"(b));
}

extern "C" __global__ void __launch_bounds__(THREADS, 2)
vq_main_kernel(const float* __restrict__ z, const float* __restrict__ emb,
               float* __restrict__ out, int n, int kchunks)
{
    extern __shared__ float sm[];
    float* zT     = sm;                         // [64][128] z tile transposed
    float* eT     = sm + DIM * NROWS_BLK;       // [64][128] emb chunk transposed
    float* zz_s   = eT + DIM * NC_CHUNK;        // [128]
    float* ee_s   = zz_s + NROWS_BLK;           // [128]
    float* minv_s = ee_s + NC_CHUNK;            // [128] running min value per row
    int*   mini_s = (int*)(minv_s + NROWS_BLK); // [128] running argmin per row
    float* red    = (float*)(mini_s + NROWS_BLK); // [32] loss reduce scratch

    const int t = threadIdx.x;
    const int rowBase = blockIdx.x * NROWS_BLK;

    // ---- load z tile, transpose into shared ----
    {
        const float4* zg4 = (const float4*)(z + (size_t)rowBase * DIM);
        #pragma unroll
        for (int i = t; i < NROWS_BLK * (DIM / 4); i += THREADS) {
            int row = i >> 4;      // DIM/4 = 16 float4 per row
            int j   = i & 15;
            float4 v = zg4[i];
            int d0 = j * 4;
            zT[(d0 + 0) * NROWS_BLK + row] = v.x;
            zT[(d0 + 1) * NROWS_BLK + row] = v.y;
            zT[(d0 + 2) * NROWS_BLK + row] = v.z;
            zT[(d0 + 3) * NROWS_BLK + row] = v.w;
        }
    }
    __syncthreads();

    // ---- per-row ||z||^2, init running min ----
    if (t < NROWS_BLK) {
        float s = 0.f;
        #pragma unroll
        for (int d = 0; d < DIM; d++) {
            float v = zT[d * NROWS_BLK + t];
            s = __fadd_rn(s, __fmul_rn(v, v));
        }
        zz_s[t] = s;
        minv_s[t] = 3.4028235e38f;
        mini_s[t] = 0x7fffffff;
    }

    const int ty = t >> 5;   // 0..7  -> 16 rows per warp
    const int tx = t & 31;   // 0..31 -> 4 codes per lane
    const int r0 = ty * 16;

    for (int cc = 0; cc < kchunks; cc++) {
        __syncthreads();  // protects eT/ee_s from previous chunk; first iter: zz/min init

        // ---- load emb chunk, transpose ----
        {
            const float4* eg4 = (const float4*)(emb + (size_t)cc * NC_CHUNK * DIM);
            #pragma unroll
            for (int i = t; i < NC_CHUNK * (DIM / 4); i += THREADS) {
                int c = i >> 4;
                int j = i & 15;
                float4 v = eg4[i];
                int d0 = j * 4;
                eT[(d0 + 0) * NC_CHUNK + c] = v.x;
                eT[(d0 + 1) * NC_CHUNK + c] = v.y;
                eT[(d0 + 2) * NC_CHUNK + c] = v.z;
                eT[(d0 + 3) * NC_CHUNK + c] = v.w;
            }
        }
        __syncthreads();
        if (t < NC_CHUNK) {
            float s = 0.f;
            #pragma unroll
            for (int d = 0; d < DIM; d++) {
                float v = eT[d * NC_CHUNK + t];
                s = __fadd_rn(s, __fmul_rn(v, v));
            }
            ee_s[t] = s;
        }
        __syncthreads();

        // ---- main dot-product loop: 16 rows (8 pairs) x 4 codes per thread ----
        unsigned long long acc[8][4];
        #pragma unroll
        for (int p = 0; p < 8; p++)
            #pragma unroll
            for (int c = 0; c < 4; c++)
                acc[p][c] = 0ULL;

        #pragma unroll 16
        for (int d = 0; d < DIM; d++) {
            const float* zrow = zT + d * NROWS_BLK + r0;
            unsigned long long zp[8];
            #pragma unroll
            for (int p = 0; p < 8; p++)
                zp[p] = *(const unsigned long long*)(zrow + 2 * p);   // LDS.64, warp-broadcast

            float4 ev = *(const float4*)(eT + d * NC_CHUNK + tx * 4); // LDS.128
            unsigned long long e0 = pack2(ev.x, ev.x);
            unsigned long long e1 = pack2(ev.y, ev.y);
            unsigned long long e2 = pack2(ev.z, ev.z);
            unsigned long long e3 = pack2(ev.w, ev.w);

            #pragma unroll
            for (int p = 0; p < 8; p++) {
                fma2(acc[p][0], zp[p], e0);
                fma2(acc[p][1], zp[p], e1);
                fma2(acc[p][2], zp[p], e2);
                fma2(acc[p][3], zp[p], e3);
            }
        }

        // ---- epilogue: distances (reference rounding order) + per-thread min ----
        float mv[16];
        int   mi[16];
        #pragma unroll
        for (int r = 0; r < 16; r++) { mv[r] = 3.4028235e38f; mi[r] = 0x7fffffff; }

        #pragma unroll
        for (int p = 0; p < 8; p++) {
            float zza = zz_s[r0 + 2 * p];
            float zzb = zz_s[r0 + 2 * p + 1];
            #pragma unroll
            for (int c = 0; c < 4; c++) {
                int cl = tx * 4 + c;
                int k  = cc * NC_CHUNK + cl;
                float a0, a1;
                unpack2(acc[p][c], a0, a1);
                float ee = ee_s[cl];
                // d = (zz + ee) - 2*dot  (each step rounded, matching reference)
                float dv0 = __fadd_rn(__fadd_rn(zza, ee), -__fmul_rn(2.0f, a0));
                float dv1 = __fadd_rn(__fadd_rn(zzb, ee), -__fmul_rn(2.0f, a1));
                if (dv0 < mv[2 * p])     { mv[2 * p] = dv0;     mi[2 * p] = k; }
                if (dv1 < mv[2 * p + 1]) { mv[2 * p + 1] = dv1; mi[2 * p + 1] = k; }
            }
        }

        // ---- warp butterfly reduce (argmin semantics: lowest index on ties) ----
        #pragma unroll
        for (int off = 16; off >= 1; off >>= 1) {
            #pragma unroll
            for (int r = 0; r < 16; r++) {
                float ov = __shfl_xor_sync(0xffffffffu, mv[r], off);
                int   oi = __shfl_xor_sync(0xffffffffu, mi[r], off);
                if (ov < mv[r] || (ov == mv[r] && oi < mi[r])) { mv[r] = ov; mi[r] = oi; }
            }
        }
        if (tx == 0) {
            #pragma unroll
            for (int r = 0; r < 16; r++) {
                int rr = r0 + r;
                if (mv[r] < minv_s[rr] || (mv[r] == minv_s[rr] && mi[r] < mini_s[rr])) {
                    minv_s[rr] = mv[r];
                    mini_s[rr] = mi[r];
                }
            }
        }
    }
    __syncthreads();

    const size_t nd = (size_t)n * DIM;

    // ---- indices output (as float) ----
    if (t < NROWS_BLK)
        out[nd + rowBase + t] = (float)mini_s[t];

    // ---- zq_st = z + (zq - z), reference rounding; accumulate loss ----
    float lsum = 0.f;
    {
        int row = t >> 1;
        int hh  = t & 1;
        int k   = mini_s[row];
        const float4* ev4 = (const float4*)(emb + (size_t)k * DIM) + hh * 8;
        float* orow = out + (size_t)(rowBase + row) * DIM + hh * 32;
        #pragma unroll
        for (int j = 0; j < 8; j++) {
            float4 v = ev4[j];
            int d0 = hh * 32 + j * 4;
            float z0 = zT[(d0 + 0) * NROWS_BLK + row];
            float z1 = zT[(d0 + 1) * NROWS_BLK + row];
            float z2 = zT[(d0 + 2) * NROWS_BLK + row];
            float z3 = zT[(d0 + 3) * NROWS_BLK + row];
            float q0 = __fadd_rn(v.x, -z0);
            float q1 = __fadd_rn(v.y, -z1);
            float q2 = __fadd_rn(v.z, -z2);
            float q3 = __fadd_rn(v.w, -z3);
            lsum = fmaf(q0, q0, lsum);
            lsum = fmaf(q1, q1, lsum);
            lsum = fmaf(q2, q2, lsum);
            lsum = fmaf(q3, q3, lsum);
            float4 o;
            o.x = __fadd_rn(z0, q0);
            o.y = __fadd_rn(z1, q1);
            o.z = __fadd_rn(z2, q2);
            o.w = __fadd_rn(z3, q3);
            *(float4*)(orow + j * 4) = o;
        }
    }
    // block reduce loss
    #pragma unroll
    for (int off = 16; off >= 1; off >>= 1)
        lsum += __shfl_xor_sync(0xffffffffu, lsum, off);
    if ((t & 31) == 0) red[t >> 5] = lsum;
    __syncthreads();
    if (t == 0) {
        float s = 0.f;
        #pragma unroll
        for (int w = 0; w < THREADS / 32; w++) s += red[w];
        g_partials[blockIdx.x] = s;
    }
}

extern "C" __global__ void vq_finalize_kernel(float* __restrict__ out, int n, int nblocks)
{
    __shared__ double sd[256];
    int t = threadIdx.x;
    double s = 0.0;
    for (int i = t; i < nblocks; i += 256) s += (double)g_partials[i];
    sd[t] = s;
    __syncthreads();
    #pragma unroll
    for (int off = 128; off >= 1; off >>= 1) {
        if (t < off) sd[t] += sd[t + off];
        __syncthreads();
    }
    if (t == 0) {
        double mean = sd[0] / ((double)n * (double)DIM);
        out[(size_t)n * DIM + n] = (float)(1.5 * mean);  // beta*mean + mean, beta=0.5
    }
}

extern "C" void kernel_launch(void* const* d_in, const int* in_sizes, int n_in,
                              void* d_out, int out_size)
{
    const float* z   = (const float*)d_in[0];   // [N, 64]
    const float* emb = (const float*)d_in[1];   // [K, 64]
    float* out = (float*)d_out;                 // [N*64 zq | N idx | 1 loss]

    int n = in_sizes[0] / DIM;                  // 262144
    int K = in_sizes[1] / DIM;                  // 1024
    int nblocks = n / NROWS_BLK;                // 2048
    int kchunks = K / NC_CHUNK;                 // 8

    size_t smem = (size_t)(DIM * NROWS_BLK       // zT
                         + DIM * NC_CHUNK        // eT
                         + NROWS_BLK             // zz
                         + NC_CHUNK              // ee
                         + NROWS_BLK             // minv
                         + NROWS_BLK             // mini
                         + 32) * sizeof(float);  // red

    cudaFuncSetAttribute(vq_main_kernel, cudaFuncAttributeMaxDynamicSharedMemorySize, (int)smem);
    vq_main_kernel<<<nblocks, THREADS, smem>>>(z, emb, out, n, kchunks);
    vq_finalize_kernel<<<1, 256>>>(out, n, nblocks);
}